// round 6
// baseline (speedup 1.0000x reference)
#include <cuda_runtime.h>
#include <math.h>

// ---------------- scratch (device globals; referenced ONLY in device code —
// passing __device__ symbols as kernel args from host yields the host shadow
// address (silently dereferenceable via ATS on GB300) — that was the R2-R5 bug.
#define NMAX 100000
__device__ __align__(16) float g_H[NMAX * 128];    // GEMM output (dense H)
__device__ __align__(16) float g_AG1[NMAX * 128];  // layer-1 agg accumulator
__device__ __align__(16) float g_AG2[NMAX * 128];  // layer-2 agg accumulator
__device__ float g_dinv[NMAX];                     // rsqrt(weighted degree)
__device__ int   g_is64;                           // edge_index is int64?

// device-side buffer selector: 1=AG1, 2=AG2, 3=H
template <int SEL>
__device__ __forceinline__ float* selbuf() {
    if (SEL == 1) return g_AG1;
    if (SEL == 2) return g_AG2;
    return g_H;
}

// ---------------- edge-index dtype detection --------------------------------
// int64 little-endian with ids < 2^31  =>  every odd int32 word is 0.
__global__ void detect_kernel(const int* ei32, int twoE) {
    __shared__ int any;
    if (threadIdx.x == 0) any = 0;
    __syncthreads();
    int lim = twoE < 8192 ? twoE : 8192;
    for (int i = threadIdx.x * 2 + 1; i < lim; i += 512)
        if (ei32[i] != 0) any = 1;
    __syncthreads();
    if (threadIdx.x == 0) g_is64 = (any == 0) ? 1 : 0;
}

__device__ __forceinline__ void load_edge(const void* ei, int E, int e,
                                          int& r, int& c) {
    if (g_is64) {
        const long long* p = (const long long*)ei;
        r = (int)p[e];
        c = (int)p[(size_t)E + e];
    } else {
        const int* p = (const int*)ei;
        r = p[e];
        c = p[(size_t)E + e];
    }
}

// ---------------- degree kernels -------------------------------------------
__global__ void deg_init_kernel(int n) {
    int i = blockIdx.x * blockDim.x + threadIdx.x;
    if (i < n) g_dinv[i] = 1.0f;  // self-loop weight
}

__global__ void deg_accum_kernel(const void* ei, const float* w, int E) {
    int e = blockIdx.x * blockDim.x + threadIdx.x;
    if (e < E) {
        int r, c;
        load_edge(ei, E, e, r, c);
        atomicAdd(&g_dinv[c], w[e]);
    }
}

__global__ void deg_fin_kernel(int n) {
    int i = blockIdx.x * blockDim.x + threadIdx.x;
    if (i < n) {
        float d = g_dinv[i];                 // deg >= 1 always
        float r = rsqrtf(d);
        r = r * (1.5f - 0.5f * d * r * r);   // Newton step: sub-ulp rsqrt
        g_dinv[i] = r;
    }
}

// ---------------- GEMM: OUT = f(X)[N,128] @ W[128,MCOLS] -------------------
// XSEL:   0 = Xarg (harness ptr), else selbuf<XSEL>()
// OUTSEL: 0 = OUTarg (d_out),     else selbuf<OUTSEL>()
// INITSEL:0 = none, else selbuf<INITSEL>()[n] = dinv[n]^2 * OUT[n] (self loop)
// IN_RELU: X -> relu(X + in_bias) on load;  OUT_SIG: sigmoid(out + out_bias)
template <int MCOLS, int XSEL, int OUTSEL, int INITSEL, bool IN_RELU, bool OUT_SIG>
__global__ __launch_bounds__(256)
void gemm_kernel(const float* Xarg, const float* W,
                 const float* in_bias, const float* out_bias,
                 float* OUTarg, int n) {
    constexpr int BN = 64;           // nodes per block
    constexpr int BK = 64;           // K chunk
    constexpr int CG = MCOLS / 4;    // col groups (4 cols each)
    constexpr int NG = 256 / CG;     // node groups
    constexpr int NPT = BN / NG;     // nodes per thread

    const float* X = (XSEL == 0) ? Xarg : selbuf<XSEL>();
    float* OUT = (OUTSEL == 0) ? OUTarg : selbuf<OUTSEL>();

    __shared__ __align__(16) float ws[BK * MCOLS];  // W chunk  [BK][MCOLS]
    __shared__ __align__(16) float xs[BN * BK];     // X chunk  [BN][BK]

    const int tid = threadIdx.x;
    const int cg = tid % CG;
    const int ng = tid / CG;
    const int node0 = blockIdx.x * BN;

    float4 acc[NPT];
#pragma unroll
    for (int j = 0; j < NPT; j++) acc[j] = make_float4(0.f, 0.f, 0.f, 0.f);

    for (int kt = 0; kt < 128; kt += BK) {
#pragma unroll
        for (int i = tid; i < BK * MCOLS / 4; i += 256) {
            ((float4*)ws)[i] = ((const float4*)(W + (size_t)kt * MCOLS))[i];
        }
#pragma unroll
        for (int i = tid; i < BN * BK / 4; i += 256) {
            int flat = i * 4;
            int nn = flat / BK;
            int kk = flat % BK;
            float4 v = make_float4(0.f, 0.f, 0.f, 0.f);
            int gn = node0 + nn;
            if (gn < n) {
                v = *(const float4*)(X + (size_t)gn * 128 + kt + kk);
                if (IN_RELU) {
                    float4 bb = *(const float4*)(in_bias + kt + kk);
                    v.x = fmaxf(v.x + bb.x, 0.f);
                    v.y = fmaxf(v.y + bb.y, 0.f);
                    v.z = fmaxf(v.z + bb.z, 0.f);
                    v.w = fmaxf(v.w + bb.w, 0.f);
                }
            }
            ((float4*)xs)[i] = v;
        }
        __syncthreads();

#pragma unroll 8
        for (int k = 0; k < BK; k++) {
            float4 wv = *(const float4*)(ws + k * MCOLS + cg * 4);
#pragma unroll
            for (int j = 0; j < NPT; j++) {
                float xv = xs[(j * NG + ng) * BK + k];
                acc[j].x = fmaf(xv, wv.x, acc[j].x);
                acc[j].y = fmaf(xv, wv.y, acc[j].y);
                acc[j].z = fmaf(xv, wv.z, acc[j].z);
                acc[j].w = fmaf(xv, wv.w, acc[j].w);
            }
        }
        __syncthreads();
    }

#pragma unroll
    for (int j = 0; j < NPT; j++) {
        int gn = node0 + j * NG + ng;
        if (gn >= n) continue;
        float4 r = acc[j];
        if (OUT_SIG) {
            float4 bb = *(const float4*)(out_bias + cg * 4);
            r.x = 1.f / (1.f + expf(-(r.x + bb.x)));
            r.y = 1.f / (1.f + expf(-(r.y + bb.y)));
            r.z = 1.f / (1.f + expf(-(r.z + bb.z)));
            r.w = 1.f / (1.f + expf(-(r.w + bb.w)));
        }
        *(float4*)(OUT + (size_t)gn * MCOLS + cg * 4) = r;
        if (INITSEL != 0) {
            float d = g_dinv[gn];
            float s = d * d;
            float4 r2 = make_float4(r.x * s, r.y * s, r.z * s, r.w * s);
            *(float4*)(selbuf<INITSEL>() + (size_t)gn * 128 + cg * 4) = r2;
        }
    }
}

// ---------------- edge aggregation: dst[c] += dinv_r*w*dinv_c * g_H[r] -----
// one warp per edge; each lane handles one float4 (32*4 = 128 feats)
template <int DST>
__global__ __launch_bounds__(256)
void agg_kernel(const void* ei, const float* w, int E) {
    int gid = blockIdx.x * blockDim.x + threadIdx.x;
    int e = gid >> 5;
    if (e >= E) return;
    int lane = gid & 31;

    int r, c;
    load_edge(ei, E, e, r, c);
    float coeff = g_dinv[r] * __ldg(&w[e]) * g_dinv[c];

    float4 v = *(const float4*)(g_H + (size_t)r * 128 + lane * 4);

    float* dst = selbuf<DST>() + (size_t)c * 128 + lane * 4;
    atomicAdd(dst + 0, coeff * v.x);
    atomicAdd(dst + 1, coeff * v.y);
    atomicAdd(dst + 2, coeff * v.z);
    atomicAdd(dst + 3, coeff * v.w);
}

// ---------------- launch ----------------------------------------------------
extern "C" void kernel_launch(void* const* d_in, const int* in_sizes, int n_in,
                              void* d_out, int out_size) {
    const float* x   = (const float*)d_in[0];
    const void*  ei  = d_in[1];
    const float* ew  = (const float*)d_in[2];
    const float* W1  = (const float*)d_in[3];
    const float* b1  = (const float*)d_in[4];
    const float* W2  = (const float*)d_in[5];
    const float* b2  = (const float*)d_in[6];
    const float* Wfc = (const float*)d_in[7];
    const float* bfc = (const float*)d_in[8];

    int N = in_sizes[0] / 128;
    int E = in_sizes[2];

    detect_kernel<<<1, 256>>>((const int*)ei, 2 * E);

    deg_init_kernel<<<(N + 255) / 256, 256>>>(N);
    deg_accum_kernel<<<(E + 255) / 256, 256>>>(ei, ew, E);
    deg_fin_kernel<<<(N + 255) / 256, 256>>>(N);

    int gb = (N + 63) / 64;
    long long tot = (long long)E * 32;
    int ablocks = (int)((tot + 255) / 256);

    // layer 1: H = x@W1 -> g_H;  g_AG1 = dinv^2*H;  g_AG1 += edge terms
    gemm_kernel<128, 0, 3, 1, false, false><<<gb, 256>>>(x, W1, nullptr,
                                                         nullptr, nullptr, N);
    agg_kernel<1><<<ablocks, 256>>>(ei, ew, E);

    // layer 2: H = relu(g_AG1 + b1)@W2 -> g_H;  g_AG2 = dinv^2*H;  += edges
    gemm_kernel<128, 1, 3, 2, true, false><<<gb, 256>>>(nullptr, W2, b1,
                                                        nullptr, nullptr, N);
    agg_kernel<2><<<ablocks, 256>>>(ei, ew, E);

    // final: d_out = sigmoid( relu(g_AG2 + b2) @ Wfc + bfc )
    gemm_kernel<64, 2, 0, 0, true, true><<<gb, 256>>>(nullptr, Wfc, b2, bfc,
                                                      (float*)d_out, N);
}

// round 7
// speedup vs baseline: 2.0516x; 2.0516x over previous
#include <cuda_runtime.h>
#include <math.h>

// ---- scratch (device globals; referenced ONLY inside device code) ----------
#define NMAX 100000
#define EMAX 1600000
__device__ __align__(16) float g_H[NMAX * 128];    // GEMM output (dense H)
__device__ __align__(16) float g_AG[NMAX * 128];   // aggregation result
__device__ float  g_dinv[NMAX];                    // rsqrt(weighted degree)
__device__ int    g_cnt[NMAX];                     // in-degree counts
__device__ int    g_rowptr[NMAX + 1];              // CSR row pointers (by dst)
__device__ int    g_pos[NMAX];                     // scatter cursors
__device__ __align__(8) float2 g_edge[EMAX];       // {src_bits, coeff} by dst
__device__ int    g_is64;                          // edge_index is int64?

// ---- edge-index dtype detection --------------------------------------------
__global__ void detect_kernel(const int* ei32, int twoE) {
    __shared__ int any;
    if (threadIdx.x == 0) any = 0;
    __syncthreads();
    int lim = twoE < 8192 ? twoE : 8192;
    for (int i = threadIdx.x * 2 + 1; i < lim; i += 512)
        if (ei32[i] != 0) any = 1;
    __syncthreads();
    if (threadIdx.x == 0) g_is64 = (any == 0) ? 1 : 0;
}

__device__ __forceinline__ void load_edge(const void* ei, int E, int e,
                                          int& r, int& c) {
    if (g_is64) {
        const long long* p = (const long long*)ei;
        r = (int)p[e];
        c = (int)p[(size_t)E + e];
    } else {
        const int* p = (const int*)ei;
        r = p[e];
        c = p[(size_t)E + e];
    }
}

// ---- degree + histogram -----------------------------------------------------
__global__ void deg_init_kernel(int n) {
    int i = blockIdx.x * blockDim.x + threadIdx.x;
    if (i < n) { g_dinv[i] = 1.0f; g_cnt[i] = 0; }   // self-loop weight = 1
}

__global__ void deg_accum_kernel(const void* ei, const float* w, int E) {
    int e = blockIdx.x * blockDim.x + threadIdx.x;
    if (e < E) {
        int r, c;
        load_edge(ei, E, e, r, c);
        atomicAdd(&g_dinv[c], w[e]);
        atomicAdd(&g_cnt[c], 1);
    }
}

__global__ void deg_fin_kernel(int n) {
    int i = blockIdx.x * blockDim.x + threadIdx.x;
    if (i < n) {
        float d = g_dinv[i];                 // deg >= 1 always
        float r = rsqrtf(d);
        r = r * (1.5f - 0.5f * d * r * r);   // Newton step: sub-ulp rsqrt
        g_dinv[i] = r;
    }
}

// ---- single-block exclusive scan of g_cnt -> g_rowptr, g_pos ---------------
__global__ __launch_bounds__(1024)
void scan_kernel(int n) {
    __shared__ int bsum[1024];
    int t = threadIdx.x;
    int chunk = (n + 1023) / 1024;
    int s = t * chunk;
    int e = min(s + chunk, n);
    int sum = 0;
    for (int i = s; i < e; i++) sum += g_cnt[i];
    bsum[t] = sum;
    __syncthreads();
    for (int off = 1; off < 1024; off <<= 1) {
        int v = 0;
        if (t >= off) v = bsum[t - off];
        __syncthreads();
        if (t >= off) bsum[t] += v;
        __syncthreads();
    }
    int run = (t == 0) ? 0 : bsum[t - 1];
    for (int i = s; i < e; i++) {
        g_rowptr[i] = run;
        g_pos[i] = run;
        run += g_cnt[i];
    }
    if (t == 1023 || e == n) g_rowptr[n] = bsum[1023];
}

// ---- scatter edges into CSR, precompute coeff = dinv_r * w * dinv_c --------
__global__ void scatter_kernel(const void* ei, const float* w, int E) {
    int e = blockIdx.x * blockDim.x + threadIdx.x;
    if (e >= E) return;
    int r, c;
    load_edge(ei, E, e, r, c);
    float coeff = g_dinv[r] * __ldg(&w[e]) * g_dinv[c];
    int p = atomicAdd(&g_pos[c], 1);
    g_edge[p] = make_float2(__int_as_float(r), coeff);
}

// ---- GEMM: OUT = f(X)[N,128] @ W[128,MCOLS] --------------------------------
// XSEL: 0 = Xarg, 1 = g_AG.   OUTSEL: 0 = OUTarg(d_out), 1 = g_H.
// IN_RELU: X -> relu(X + in_bias);   OUT_SIG: sigmoid(out + out_bias)
template <int MCOLS, int XSEL, int OUTSEL, bool IN_RELU, bool OUT_SIG>
__global__ __launch_bounds__(256)
void gemm_kernel(const float* Xarg, const float* W,
                 const float* in_bias, const float* out_bias,
                 float* OUTarg, int n) {
    constexpr int BN = 64;           // nodes per block
    constexpr int BK = 64;           // K chunk
    constexpr int CG = MCOLS / 4;    // col groups (4 cols each)
    constexpr int NG = 256 / CG;     // node groups
    constexpr int NPT = BN / NG;     // nodes per thread

    const float* X = (XSEL == 0) ? Xarg : g_AG;
    float* OUT = (OUTSEL == 0) ? OUTarg : g_H;

    __shared__ __align__(16) float ws[BK * MCOLS];
    __shared__ __align__(16) float xs[BN * BK];

    const int tid = threadIdx.x;
    const int cg = tid % CG;
    const int ng = tid / CG;
    const int node0 = blockIdx.x * BN;

    float4 acc[NPT];
#pragma unroll
    for (int j = 0; j < NPT; j++) acc[j] = make_float4(0.f, 0.f, 0.f, 0.f);

    for (int kt = 0; kt < 128; kt += BK) {
#pragma unroll
        for (int i = tid; i < BK * MCOLS / 4; i += 256) {
            ((float4*)ws)[i] = ((const float4*)(W + (size_t)kt * MCOLS))[i];
        }
#pragma unroll
        for (int i = tid; i < BN * BK / 4; i += 256) {
            int flat = i * 4;
            int nn = flat / BK;
            int kk = flat % BK;
            float4 v = make_float4(0.f, 0.f, 0.f, 0.f);
            int gn = node0 + nn;
            if (gn < n) {
                v = *(const float4*)(X + (size_t)gn * 128 + kt + kk);
                if (IN_RELU) {
                    float4 bb = *(const float4*)(in_bias + kt + kk);
                    v.x = fmaxf(v.x + bb.x, 0.f);
                    v.y = fmaxf(v.y + bb.y, 0.f);
                    v.z = fmaxf(v.z + bb.z, 0.f);
                    v.w = fmaxf(v.w + bb.w, 0.f);
                }
            }
            ((float4*)xs)[i] = v;
        }
        __syncthreads();

#pragma unroll 8
        for (int k = 0; k < BK; k++) {
            float4 wv = *(const float4*)(ws + k * MCOLS + cg * 4);
#pragma unroll
            for (int j = 0; j < NPT; j++) {
                float xv = xs[(j * NG + ng) * BK + k];
                acc[j].x = fmaf(xv, wv.x, acc[j].x);
                acc[j].y = fmaf(xv, wv.y, acc[j].y);
                acc[j].z = fmaf(xv, wv.z, acc[j].z);
                acc[j].w = fmaf(xv, wv.w, acc[j].w);
            }
        }
        __syncthreads();
    }

#pragma unroll
    for (int j = 0; j < NPT; j++) {
        int gn = node0 + j * NG + ng;
        if (gn >= n) continue;
        float4 r = acc[j];
        if (OUT_SIG) {
            float4 bb = *(const float4*)(out_bias + cg * 4);
            r.x = 1.f / (1.f + expf(-(r.x + bb.x)));
            r.y = 1.f / (1.f + expf(-(r.y + bb.y)));
            r.z = 1.f / (1.f + expf(-(r.z + bb.z)));
            r.w = 1.f / (1.f + expf(-(r.w + bb.w)));
        }
        *(float4*)(OUT + (size_t)gn * MCOLS + cg * 4) = r;
    }
}

// ---- CSR aggregation: g_AG[n] = dinv[n]^2*g_H[n] + sum_e coeff_e*g_H[src_e]
// one warp per destination node; lane owns one float4 (4 of 128 feats)
__global__ __launch_bounds__(256)
void agg_csr_kernel(int n) {
    int gid = blockIdx.x * blockDim.x + threadIdx.x;
    int node = gid >> 5;
    if (node >= n) return;
    int lane = gid & 31;

    int beg = g_rowptr[node];
    int end = g_rowptr[node + 1];

    float d = g_dinv[node];
    float s = d * d;
    float4 acc = *(const float4*)(g_H + (size_t)node * 128 + lane * 4);
    acc.x *= s; acc.y *= s; acc.z *= s; acc.w *= s;

    int j = beg;
    for (; j + 1 < end; j += 2) {
        float2 e0 = g_edge[j];
        float2 e1 = g_edge[j + 1];
        int s0 = __float_as_int(e0.x);
        int s1 = __float_as_int(e1.x);
        float4 v0 = *(const float4*)(g_H + (size_t)s0 * 128 + lane * 4);
        float4 v1 = *(const float4*)(g_H + (size_t)s1 * 128 + lane * 4);
        acc.x = fmaf(e0.y, v0.x, acc.x);
        acc.y = fmaf(e0.y, v0.y, acc.y);
        acc.z = fmaf(e0.y, v0.z, acc.z);
        acc.w = fmaf(e0.y, v0.w, acc.w);
        acc.x = fmaf(e1.y, v1.x, acc.x);
        acc.y = fmaf(e1.y, v1.y, acc.y);
        acc.z = fmaf(e1.y, v1.z, acc.z);
        acc.w = fmaf(e1.y, v1.w, acc.w);
    }
    if (j < end) {
        float2 e0 = g_edge[j];
        int s0 = __float_as_int(e0.x);
        float4 v0 = *(const float4*)(g_H + (size_t)s0 * 128 + lane * 4);
        acc.x = fmaf(e0.y, v0.x, acc.x);
        acc.y = fmaf(e0.y, v0.y, acc.y);
        acc.z = fmaf(e0.y, v0.z, acc.z);
        acc.w = fmaf(e0.y, v0.w, acc.w);
    }

    *(float4*)(g_AG + (size_t)node * 128 + lane * 4) = acc;
}

// ---- launch ------------------------------------------------------------------
extern "C" void kernel_launch(void* const* d_in, const int* in_sizes, int n_in,
                              void* d_out, int out_size) {
    const float* x   = (const float*)d_in[0];
    const void*  ei  = d_in[1];
    const float* ew  = (const float*)d_in[2];
    const float* W1  = (const float*)d_in[3];
    const float* b1  = (const float*)d_in[4];
    const float* W2  = (const float*)d_in[5];
    const float* b2  = (const float*)d_in[6];
    const float* Wfc = (const float*)d_in[7];
    const float* bfc = (const float*)d_in[8];

    int N = in_sizes[0] / 128;
    int E = in_sizes[2];

    detect_kernel<<<1, 256>>>((const int*)ei, 2 * E);

    // degrees + counts, then CSR build (coeff precomputed once)
    deg_init_kernel<<<(N + 255) / 256, 256>>>(N);
    deg_accum_kernel<<<(E + 255) / 256, 256>>>(ei, ew, E);
    deg_fin_kernel<<<(N + 255) / 256, 256>>>(N);
    scan_kernel<<<1, 1024>>>(N);
    scatter_kernel<<<(E + 255) / 256, 256>>>(ei, ew, E);

    int gb = (N + 63) / 64;
    int awarps = (N * 32 + 255) / 256;

    // layer 1: g_H = x@W1;  g_AG = self + CSR-gather
    gemm_kernel<128, 0, 1, false, false><<<gb, 256>>>(x, W1, nullptr,
                                                      nullptr, nullptr, N);
    agg_csr_kernel<<<awarps, 256>>>(N);

    // layer 2: g_H = relu(g_AG + b1)@W2;  g_AG = self + CSR-gather
    gemm_kernel<128, 1, 1, true, false><<<gb, 256>>>(nullptr, W2, b1,
                                                     nullptr, nullptr, N);
    agg_csr_kernel<<<awarps, 256>>>(N);

    // final: d_out = sigmoid( relu(g_AG + b2) @ Wfc + bfc )
    gemm_kernel<64, 1, 0, true, true><<<gb, 256>>>(nullptr, Wfc, b2, bfc,
                                                   (float*)d_out, N);
}

// round 8
// speedup vs baseline: 2.1248x; 1.0357x over previous
#include <cuda_runtime.h>
#include <math.h>

typedef unsigned long long ull;

// ---- scratch (device globals; referenced ONLY inside device code) ----------
#define NMAX 100000
#define EMAX 1600000
__device__ __align__(16) float g_H[NMAX * 128];    // GEMM output (dense H)
__device__ __align__(16) float g_AG[NMAX * 128];   // aggregation result
__device__ float  g_dinv[NMAX];                    // rsqrt(weighted degree)
__device__ int    g_cnt[NMAX];                     // in-degree counts
__device__ int    g_rowptr[NMAX + 1];              // CSR row pointers (by dst)
__device__ int    g_pos[NMAX];                     // scatter cursors
__device__ __align__(8) float2 g_edge[EMAX];       // {src_bits, coeff} by dst
__device__ int    g_is64;                          // edge_index is int64?

// ---- packed fp32x2 helpers (FFMA2 path: 2x fp32 FMA throughput) ------------
__device__ __forceinline__ ull ffma2(ull a, ull b, ull c) {
    ull d;
    asm("fma.rn.f32x2 %0, %1, %2, %3;" : "=l"(d) : "l"(a), "l"(b), "l"(c));
    return d;
}
__device__ __forceinline__ ull pack2(float x, float y) {
    ull d;
    asm("mov.b64 %0, {%1, %2};" : "=l"(d) : "f"(x), "f"(y));
    return d;
}
__device__ __forceinline__ float2 unpack2(ull v) {
    float2 r;
    asm("mov.b64 {%0, %1}, %2;" : "=f"(r.x), "=f"(r.y) : "l"(v));
    return r;
}

// ---- edge-index dtype detection --------------------------------------------
__global__ void detect_kernel(const int* ei32, int twoE) {
    __shared__ int any;
    if (threadIdx.x == 0) any = 0;
    __syncthreads();
    int lim = twoE < 8192 ? twoE : 8192;
    for (int i = threadIdx.x * 2 + 1; i < lim; i += 512)
        if (ei32[i] != 0) any = 1;
    __syncthreads();
    if (threadIdx.x == 0) g_is64 = (any == 0) ? 1 : 0;
}

__device__ __forceinline__ void load_edge(const void* ei, int E, int e,
                                          int& r, int& c) {
    if (g_is64) {
        const long long* p = (const long long*)ei;
        r = (int)p[e];
        c = (int)p[(size_t)E + e];
    } else {
        const int* p = (const int*)ei;
        r = p[e];
        c = p[(size_t)E + e];
    }
}

// ---- degree + histogram ------------------------------------------------------
__global__ void deg_init_kernel(int n) {
    int i = blockIdx.x * blockDim.x + threadIdx.x;
    if (i < n) { g_dinv[i] = 1.0f; g_cnt[i] = 0; }   // self-loop weight = 1
}

__global__ void deg_accum_kernel(const void* ei, const float* w, int E) {
    int e = blockIdx.x * blockDim.x + threadIdx.x;
    if (e < E) {
        int r, c;
        load_edge(ei, E, e, r, c);
        atomicAdd(&g_dinv[c], w[e]);
        atomicAdd(&g_cnt[c], 1);
    }
}

__global__ void deg_fin_kernel(int n) {
    int i = blockIdx.x * blockDim.x + threadIdx.x;
    if (i < n) {
        float d = g_dinv[i];                 // deg >= 1 always
        float r = rsqrtf(d);
        r = r * (1.5f - 0.5f * d * r * r);   // Newton step: sub-ulp rsqrt
        g_dinv[i] = r;
    }
}

// ---- single-block exclusive scan of g_cnt -> g_rowptr, g_pos ----------------
__global__ __launch_bounds__(1024)
void scan_kernel(int n) {
    __shared__ int bsum[1024];
    int t = threadIdx.x;
    int chunk = (n + 1023) / 1024;
    int s = t * chunk;
    int e = min(s + chunk, n);
    int sum = 0;
    for (int i = s; i < e; i++) sum += g_cnt[i];
    bsum[t] = sum;
    __syncthreads();
    for (int off = 1; off < 1024; off <<= 1) {
        int v = 0;
        if (t >= off) v = bsum[t - off];
        __syncthreads();
        if (t >= off) bsum[t] += v;
        __syncthreads();
    }
    int run = (t == 0) ? 0 : bsum[t - 1];
    for (int i = s; i < e; i++) {
        g_rowptr[i] = run;
        g_pos[i] = run;
        run += g_cnt[i];
    }
    if (t == 1023 || e == n) g_rowptr[n] = bsum[1023];
}

// ---- scatter edges into CSR, precompute coeff = dinv_r * w * dinv_c ---------
__global__ void scatter_kernel(const void* ei, const float* w, int E) {
    int e = blockIdx.x * blockDim.x + threadIdx.x;
    if (e >= E) return;
    int r, c;
    load_edge(ei, E, e, r, c);
    float coeff = g_dinv[r] * __ldg(&w[e]) * g_dinv[c];
    int p = atomicAdd(&g_pos[c], 1);
    g_edge[p] = make_float2(__int_as_float(r), coeff);
}

// ---- GEMM (FFMA2): OUT = f(X)[N,128] @ W[128,MCOLS] -------------------------
// X tile stored transposed in smem (xs_t[k][node], stride BNP) so node-pairs
// load directly as packed f32x2 operands; W column scalars dup'd via mov.b64.
// XSEL: 0 = Xarg, 1 = g_AG.   OUTSEL: 0 = OUTarg(d_out), 1 = g_H.
template <int MCOLS, int XSEL, int OUTSEL, bool IN_RELU, bool OUT_SIG>
__global__ __launch_bounds__(256)
void gemm_kernel(const float* Xarg, const float* W,
                 const float* in_bias, const float* out_bias,
                 float* OUTarg, int n) {
    constexpr int BN = 64;            // nodes per block
    constexpr int BK = 64;            // K chunk
    constexpr int BNP = 68;           // padded node stride (16B-aligned rows)
    constexpr int CG = MCOLS / 4;     // col groups (4 cols each): 32 or 16
    constexpr int NG = 256 / CG;      // node groups: 8 or 16
    constexpr int NPT = BN / NG;      // nodes per thread: 8 or 4
    constexpr int NPP = NPT / 2;      // node pairs per thread: 4 or 2

    const float* X = (XSEL == 0) ? Xarg : g_AG;
    float* OUT = (OUTSEL == 0) ? OUTarg : g_H;

    __shared__ __align__(16) float ws[BK * MCOLS];   // W chunk [BK][MCOLS]
    __shared__ __align__(16) float xs[BK * BNP];     // X chunk transposed

    const int tid = threadIdx.x;
    const int cg = tid % CG;
    const int ng = tid / CG;
    const int node0 = blockIdx.x * BN;

    ull acc[4][NPP];
#pragma unroll
    for (int c = 0; c < 4; c++)
#pragma unroll
        for (int p = 0; p < NPP; p++) acc[c][p] = 0ull;

    for (int kt = 0; kt < 128; kt += BK) {
        // load W chunk (coalesced float4)
#pragma unroll
        for (int i = tid; i < BK * MCOLS / 4; i += 256) {
            ((float4*)ws)[i] = ((const float4*)(W + (size_t)kt * MCOLS))[i];
        }
        // load X chunk, optional relu(x+b), store TRANSPOSED
#pragma unroll
        for (int i = tid; i < BN * BK / 4; i += 256) {
            int flat = i * 4;
            int nn = flat / BK;
            int kk = flat % BK;
            float4 v = make_float4(0.f, 0.f, 0.f, 0.f);
            int gn = node0 + nn;
            if (gn < n) {
                v = *(const float4*)(X + (size_t)gn * 128 + kt + kk);
                if (IN_RELU) {
                    float4 bb = *(const float4*)(in_bias + kt + kk);
                    v.x = fmaxf(v.x + bb.x, 0.f);
                    v.y = fmaxf(v.y + bb.y, 0.f);
                    v.z = fmaxf(v.z + bb.z, 0.f);
                    v.w = fmaxf(v.w + bb.w, 0.f);
                }
            }
            xs[(kk + 0) * BNP + nn] = v.x;
            xs[(kk + 1) * BNP + nn] = v.y;
            xs[(kk + 2) * BNP + nn] = v.z;
            xs[(kk + 3) * BNP + nn] = v.w;
        }
        __syncthreads();

#pragma unroll 8
        for (int k = 0; k < BK; k++) {
            float4 wv = *(const float4*)(ws + k * MCOLS + cg * 4);
            ull w0 = pack2(wv.x, wv.x);
            ull w1 = pack2(wv.y, wv.y);
            ull w2 = pack2(wv.z, wv.z);
            ull w3 = pack2(wv.w, wv.w);
            const ulonglong2* xp =
                (const ulonglong2*)(xs + k * BNP + ng * NPT);
#pragma unroll
            for (int q = 0; q < NPP / 2; q++) {
                ulonglong2 xv = xp[q];   // two node-pairs (broadcast LDS.128)
                acc[0][2 * q]     = ffma2(xv.x, w0, acc[0][2 * q]);
                acc[1][2 * q]     = ffma2(xv.x, w1, acc[1][2 * q]);
                acc[2][2 * q]     = ffma2(xv.x, w2, acc[2][2 * q]);
                acc[3][2 * q]     = ffma2(xv.x, w3, acc[3][2 * q]);
                acc[0][2 * q + 1] = ffma2(xv.y, w0, acc[0][2 * q + 1]);
                acc[1][2 * q + 1] = ffma2(xv.y, w1, acc[1][2 * q + 1]);
                acc[2][2 * q + 1] = ffma2(xv.y, w2, acc[2][2 * q + 1]);
                acc[3][2 * q + 1] = ffma2(xv.y, w3, acc[3][2 * q + 1]);
            }
        }
        __syncthreads();
    }

    // epilogue: unpack node pairs, apply optional sigmoid, store float4
#pragma unroll
    for (int p = 0; p < NPP; p++) {
        float2 c0 = unpack2(acc[0][p]);
        float2 c1 = unpack2(acc[1][p]);
        float2 c2 = unpack2(acc[2][p]);
        float2 c3 = unpack2(acc[3][p]);
#pragma unroll
        for (int h = 0; h < 2; h++) {
            int gn = node0 + ng * NPT + 2 * p + h;
            if (gn >= n) continue;
            float4 r = h ? make_float4(c0.y, c1.y, c2.y, c3.y)
                         : make_float4(c0.x, c1.x, c2.x, c3.x);
            if (OUT_SIG) {
                float4 bb = *(const float4*)(out_bias + cg * 4);
                r.x = 1.f / (1.f + expf(-(r.x + bb.x)));
                r.y = 1.f / (1.f + expf(-(r.y + bb.y)));
                r.z = 1.f / (1.f + expf(-(r.z + bb.z)));
                r.w = 1.f / (1.f + expf(-(r.w + bb.w)));
            }
            *(float4*)(OUT + (size_t)gn * MCOLS + cg * 4) = r;
        }
    }
}

// ---- CSR aggregation: g_AG[n] = dinv[n]^2*g_H[n] + sum_e coeff_e*g_H[src_e]
__global__ __launch_bounds__(256)
void agg_csr_kernel(int n) {
    int gid = blockIdx.x * blockDim.x + threadIdx.x;
    int node = gid >> 5;
    if (node >= n) return;
    int lane = gid & 31;

    int beg = g_rowptr[node];
    int end = g_rowptr[node + 1];

    float d = g_dinv[node];
    float s = d * d;
    float4 acc = *(const float4*)(g_H + (size_t)node * 128 + lane * 4);
    acc.x *= s; acc.y *= s; acc.z *= s; acc.w *= s;

    int j = beg;
    for (; j + 1 < end; j += 2) {
        float2 e0 = g_edge[j];
        float2 e1 = g_edge[j + 1];
        int s0 = __float_as_int(e0.x);
        int s1 = __float_as_int(e1.x);
        float4 v0 = *(const float4*)(g_H + (size_t)s0 * 128 + lane * 4);
        float4 v1 = *(const float4*)(g_H + (size_t)s1 * 128 + lane * 4);
        acc.x = fmaf(e0.y, v0.x, acc.x);
        acc.y = fmaf(e0.y, v0.y, acc.y);
        acc.z = fmaf(e0.y, v0.z, acc.z);
        acc.w = fmaf(e0.y, v0.w, acc.w);
        acc.x = fmaf(e1.y, v1.x, acc.x);
        acc.y = fmaf(e1.y, v1.y, acc.y);
        acc.z = fmaf(e1.y, v1.z, acc.z);
        acc.w = fmaf(e1.y, v1.w, acc.w);
    }
    if (j < end) {
        float2 e0 = g_edge[j];
        int s0 = __float_as_int(e0.x);
        float4 v0 = *(const float4*)(g_H + (size_t)s0 * 128 + lane * 4);
        acc.x = fmaf(e0.y, v0.x, acc.x);
        acc.y = fmaf(e0.y, v0.y, acc.y);
        acc.z = fmaf(e0.y, v0.z, acc.z);
        acc.w = fmaf(e0.y, v0.w, acc.w);
    }

    *(float4*)(g_AG + (size_t)node * 128 + lane * 4) = acc;
}

// ---- launch -------------------------------------------------------------------
extern "C" void kernel_launch(void* const* d_in, const int* in_sizes, int n_in,
                              void* d_out, int out_size) {
    const float* x   = (const float*)d_in[0];
    const void*  ei  = d_in[1];
    const float* ew  = (const float*)d_in[2];
    const float* W1  = (const float*)d_in[3];
    const float* b1  = (const float*)d_in[4];
    const float* W2  = (const float*)d_in[5];
    const float* b2  = (const float*)d_in[6];
    const float* Wfc = (const float*)d_in[7];
    const float* bfc = (const float*)d_in[8];

    int N = in_sizes[0] / 128;
    int E = in_sizes[2];

    int gb = (N + 63) / 64;
    int awarps = (N * 32 + 255) / 256;
    int eb = (E + 255) / 256;
    int nb = (N + 255) / 256;

    // fork a side stream: CSR build runs concurrently with layer-1 GEMM.
    // (kernel_launch is invoked only a handful of times; resources not freed.)
    cudaStream_t s2;
    cudaStreamCreateWithFlags(&s2, cudaStreamNonBlocking);
    cudaEvent_t evF, evJ;
    cudaEventCreateWithFlags(&evF, cudaEventDisableTiming);
    cudaEventCreateWithFlags(&evJ, cudaEventDisableTiming);

    cudaEventRecord(evF, 0);
    cudaStreamWaitEvent(s2, evF, 0);

    // side stream: edge dtype detect, degrees, CSR build (coeff precomputed)
    detect_kernel<<<1, 256, 0, s2>>>((const int*)ei, 2 * E);
    deg_init_kernel<<<nb, 256, 0, s2>>>(N);
    deg_accum_kernel<<<eb, 256, 0, s2>>>(ei, ew, E);
    deg_fin_kernel<<<nb, 256, 0, s2>>>(N);
    scan_kernel<<<1, 1024, 0, s2>>>(N);
    scatter_kernel<<<eb, 256, 0, s2>>>(ei, ew, E);
    cudaEventRecord(evJ, s2);

    // main stream: layer-1 GEMM overlaps the build
    gemm_kernel<128, 0, 1, false, false><<<gb, 256>>>(x, W1, nullptr,
                                                      nullptr, nullptr, N);
    cudaStreamWaitEvent(0, evJ, 0);

    // layer 1 aggregation
    agg_csr_kernel<<<awarps, 256>>>(N);

    // layer 2: g_H = relu(g_AG + b1)@W2;  g_AG = self + CSR-gather
    gemm_kernel<128, 1, 1, true, false><<<gb, 256>>>(nullptr, W2, b1,
                                                     nullptr, nullptr, N);
    agg_csr_kernel<<<awarps, 256>>>(N);

    // final: d_out = sigmoid( relu(g_AG + b2) @ Wfc + bfc )
    gemm_kernel<64, 1, 0, true, true><<<gb, 256>>>(nullptr, Wfc, b2, bfc,
                                                   (float*)d_out, N);
}